// round 6
// baseline (speedup 1.0000x reference)
#include <cuda_runtime.h>
#include <cuda_fp16.h>
#include <cstdint>
#include <math.h>

// Problem constants
#define B_    16
#define S_    2048
#define D_    1024
#define M_    128
#define H_    16
#define DH_   64
#define INNER_ 1024

// ---------------------------------------------------------------------------
// Scratch (static device arrays: alloc APIs are forbidden)
// ---------------------------------------------------------------------------
__device__ __half g_xnh [B_ * S_ * D_];           // 67 MB  (LN(x) in f16)
__device__ __half g_lnh [B_ * M_ * D_];           // 4 MB   (LN(latents) f16)
__device__ __half g_Wqh [INNER_ * D_];            // 2 MB
__device__ __half g_Wkvh[2 * INNER_ * D_];        // 4 MB
__device__ __half g_Woh [D_ * INNER_];            // 2 MB
__device__ float  g_q   [B_ * M_ * INNER_];       // 8 MB   (fp32 q)
__device__ float  g_kv  [B_ * S_ * 2 * INNER_];   // 268 MB (fp32 kv)
__device__ __half g_ath [B_ * M_ * INNER_];       // 4 MB   (attention out f16)

// ---------------------------------------------------------------------------
// Helpers
// ---------------------------------------------------------------------------
__device__ __forceinline__ uint32_t smem_u32(const void* p) {
    uint32_t a;
    asm("{ .reg .u64 t; cvta.to.shared.u64 t, %1; cvt.u32.u64 %0, t; }"
        : "=r"(a) : "l"(p));
    return a;
}

#define CP_ASYNC16(dst, src) \
    asm volatile("cp.async.cg.shared.global [%0], [%1], 16;" \
                 :: "r"(dst), "l"(src))
#define CP_COMMIT() asm volatile("cp.async.commit_group;" ::: "memory")
#define CP_WAIT(n)  asm volatile("cp.async.wait_group %0;" :: "n"(n) : "memory")

#define LDMATRIX_X4(r0, r1, r2, r3, addr) \
    asm volatile("ldmatrix.sync.aligned.m8n8.x4.shared.b16 {%0,%1,%2,%3}, [%4];" \
                 : "=r"(r0), "=r"(r1), "=r"(r2), "=r"(r3) : "r"(addr))

#define MMA16816(c0, c1, c2, c3, a0, a1, a2, a3, b0, b1) \
    asm volatile("mma.sync.aligned.m16n8k16.row.col.f32.f16.f16.f32 " \
                 "{%0,%1,%2,%3}, {%4,%5,%6,%7}, {%8,%9}, {%0,%1,%2,%3};" \
                 : "+f"(c0), "+f"(c1), "+f"(c2), "+f"(c3) \
                 : "r"(a0), "r"(a1), "r"(a2), "r"(a3), "r"(b0), "r"(b1))

// f32x2 packed FMA (compiled fine on this target — verified in R5 error log)
__device__ __forceinline__ unsigned long long ffma2(unsigned long long a,
                                                    unsigned long long b,
                                                    unsigned long long c) {
    unsigned long long d;
    asm("fma.rn.f32x2 %0, %1, %2, %3;" : "=l"(d) : "l"(a), "l"(b), "l"(c));
    return d;
}
__device__ __forceinline__ unsigned long long pk2(float lo, float hi) {
    unsigned long long r;
    asm("mov.b64 %0, {%1, %2};" : "=l"(r) : "f"(lo), "f"(hi));
    return r;
}
__device__ __forceinline__ void upk2(unsigned long long v, float& lo, float& hi) {
    asm("mov.b64 {%0, %1}, %2;" : "=f"(lo), "=f"(hi) : "l"(v));
}

// ---------------------------------------------------------------------------
// LayerNorm: one block per row of 1024, 256 threads, f16 output
// ---------------------------------------------------------------------------
__global__ void __launch_bounds__(256)
layernorm_h_kernel(const float* __restrict__ x, const float* __restrict__ gamma,
                   const float* __restrict__ beta, __half* __restrict__ out) {
    int row = blockIdx.x;
    int t   = threadIdx.x;
    const float4* xr = (const float4*)(x + (size_t)row * D_);
    float4 v = xr[t];
    float s  = v.x + v.y + v.z + v.w;
    float ss = v.x * v.x + v.y * v.y + v.z * v.z + v.w * v.w;

    __shared__ float red[64];
    const unsigned mask = 0xffffffffu;
#pragma unroll
    for (int o = 16; o > 0; o >>= 1) {
        s  += __shfl_xor_sync(mask, s, o);
        ss += __shfl_xor_sync(mask, ss, o);
    }
    int wid = t >> 5, lane = t & 31;
    if (lane == 0) { red[wid] = s; red[32 + wid] = ss; }
    __syncthreads();
    if (t < 32) {
        float s2  = (lane < 8) ? red[lane]      : 0.f;
        float ss2 = (lane < 8) ? red[32 + lane] : 0.f;
#pragma unroll
        for (int o = 4; o > 0; o >>= 1) {
            s2  += __shfl_xor_sync(mask, s2, o);
            ss2 += __shfl_xor_sync(mask, ss2, o);
        }
        if (lane == 0) { red[0] = s2; red[1] = ss2; }
    }
    __syncthreads();
    float mu   = red[0] * (1.f / D_);
    float var  = red[1] * (1.f / D_) - mu * mu;
    float rstd = rsqrtf(var + 1e-5f);

    float4 g  = ((const float4*)gamma)[t];
    float4 bb = ((const float4*)beta)[t];
    float ox = (v.x - mu) * rstd * g.x + bb.x;
    float oy = (v.y - mu) * rstd * g.y + bb.y;
    float oz = (v.z - mu) * rstd * g.z + bb.z;
    float ow = (v.w - mu) * rstd * g.w + bb.w;
    __half2* op = (__half2*)(out + (size_t)row * D_);
    op[t * 2]     = __floats2half2_rn(ox, oy);
    op[t * 2 + 1] = __floats2half2_rn(oz, ow);
}

// ---------------------------------------------------------------------------
// fp32 -> fp16 convert (weights)
// ---------------------------------------------------------------------------
__global__ void __launch_bounds__(256)
conv_f2h(const float* __restrict__ in, __half* __restrict__ out, int n4) {
    int i = blockIdx.x * 256 + threadIdx.x;
    if (i < n4) {
        float4 v = ((const float4*)in)[i];
        __half2* op = (__half2*)out;
        op[i * 2]     = __floats2half2_rn(v.x, v.y);
        op[i * 2 + 1] = __floats2half2_rn(v.z, v.w);
    }
}

// ---------------------------------------------------------------------------
// HGEMM via mma.sync (HMMA): C_f32[M,N] = alpha * A_h[M,K] @ B_h[N,K]^T
// Both operands K-major ("NT"), which is exactly mma .row.col:
//   A row-major M x K, B (stored N x K row-major) == col-major K x N.
// 128x128x32 tiles, 256 threads = 8 warps in 2(M) x 4(N); warp tile 64x32.
// cp.async double-buffered smem, padded rows (stride 40 halfs) for
// conflict-free ldmatrix (row-to-row bank shift pattern 0,20,8,28,16,4,24,12).
//
// Fragment maps (derived against PTX ISA m16n8k16 spec):
//  A x4: lane addr row = ar + (lane&15), col = kk + ((lane>>4)<<3)
//        -> regs {a0,a1,a2,a3} = {r0-7/k0-7, r8-15/k0-7, r0-7/k8-15, r8-15/k8-15}
//  B x4 (two n-tiles at once): row = nr + (lane&7) + ((lane>>4)<<3),
//        col = kk + (((lane>>3)&1)<<3)
//        -> regs {n-lo/k-lo, n-lo/k-hi, n-hi/k-lo, n-hi/k-hi}
// ---------------------------------------------------------------------------
#define BM 128
#define BN 128
#define BKH 32                   // halfs per k-tile
#define ASTR 40                  // padded row stride in halfs (80 bytes)
#define TILE_H (BM * ASTR)       // 5120 halfs = 10240 bytes per operand buffer

__global__ void __launch_bounds__(256)
hgemm_mma(const __half* __restrict__ A, const __half* __restrict__ B,
          float* __restrict__ C, int Kdim, int Ndim, float alpha) {
    __shared__ __half sA[2][TILE_H];
    __shared__ __half sB[2][TILE_H];

    int tid    = threadIdx.x;
    int lane   = tid & 31;
    int wid    = tid >> 5;
    int warp_m = wid & 1;        // 0..1 -> 64 rows each
    int warp_n = wid >> 1;       // 0..3 -> 32 cols each
    int m0     = blockIdx.y * BM;
    int n0     = blockIdx.x * BN;

    const __half* Ab = A + (size_t)m0 * Kdim;
    const __half* Bb = B + (size_t)n0 * Kdim;

    uint32_t sAu = smem_u32(&sA[0][0]);
    uint32_t sBu = smem_u32(&sB[0][0]);

    float c[4][4][4];
#pragma unroll
    for (int i = 0; i < 4; i++)
#pragma unroll
        for (int j = 0; j < 4; j++)
#pragma unroll
            for (int k = 0; k < 4; k++) c[i][j][k] = 0.f;

    // per-thread cp.async slots: 512 16B-chunks per operand per tile
    int r0 = tid >> 2;               // 0..63
    int c0chunk = tid & 3;
    int r1 = (tid + 256) >> 2;       // 64..127

    int NT = Kdim / BKH;

    // prologue: tile 0 -> buffer 0
    {
        int k0 = 0;
        uint32_t dA0 = sAu + (uint32_t)(r0 * 80 + c0chunk * 16);
        uint32_t dA1 = sAu + (uint32_t)(r1 * 80 + c0chunk * 16);
        uint32_t dB0 = sBu + (uint32_t)(r0 * 80 + c0chunk * 16);
        uint32_t dB1 = sBu + (uint32_t)(r1 * 80 + c0chunk * 16);
        CP_ASYNC16(dA0, Ab + (size_t)r0 * Kdim + k0 + c0chunk * 8);
        CP_ASYNC16(dA1, Ab + (size_t)r1 * Kdim + k0 + c0chunk * 8);
        CP_ASYNC16(dB0, Bb + (size_t)r0 * Kdim + k0 + c0chunk * 8);
        CP_ASYNC16(dB1, Bb + (size_t)r1 * Kdim + k0 + c0chunk * 8);
        CP_COMMIT();
    }

    for (int kt = 0; kt < NT; kt++) {
        int buf = kt & 1;

        if (kt + 1 < NT) {
            int nb = buf ^ 1;
            int k0 = (kt + 1) * BKH;
            uint32_t aoff = (uint32_t)(nb * TILE_H * 2);
            uint32_t dA0 = sAu + aoff + (uint32_t)(r0 * 80 + c0chunk * 16);
            uint32_t dA1 = sAu + aoff + (uint32_t)(r1 * 80 + c0chunk * 16);
            uint32_t dB0 = sBu + aoff + (uint32_t)(r0 * 80 + c0chunk * 16);
            uint32_t dB1 = sBu + aoff + (uint32_t)(r1 * 80 + c0chunk * 16);
            CP_ASYNC16(dA0, Ab + (size_t)r0 * Kdim + k0 + c0chunk * 8);
            CP_ASYNC16(dA1, Ab + (size_t)r1 * Kdim + k0 + c0chunk * 8);
            CP_ASYNC16(dB0, Bb + (size_t)r0 * Kdim + k0 + c0chunk * 8);
            CP_ASYNC16(dB1, Bb + (size_t)r1 * Kdim + k0 + c0chunk * 8);
            CP_COMMIT();
            CP_WAIT(1);                 // tile kt complete
        } else {
            CP_WAIT(0);
        }
        __syncthreads();

        uint32_t baseA = sAu + (uint32_t)(buf * TILE_H * 2);
        uint32_t baseB = sBu + (uint32_t)(buf * TILE_H * 2);

#pragma unroll
        for (int kk = 0; kk < BKH; kk += 16) {
            uint32_t a[4][4];
#pragma unroll
            for (int mt = 0; mt < 4; mt++) {
                int r = warp_m * 64 + mt * 16 + (lane & 15);
                int cc = kk + ((lane >> 4) << 3);
                uint32_t addr = baseA + (uint32_t)(r * 80 + cc * 2);
                LDMATRIX_X4(a[mt][0], a[mt][1], a[mt][2], a[mt][3], addr);
            }
            uint32_t bf[4][2];
#pragma unroll
            for (int nb = 0; nb < 2; nb++) {
                int r = warp_n * 32 + nb * 16 + (lane & 7) + ((lane >> 4) << 3);
                int cc = kk + (((lane >> 3) & 1) << 3);
                uint32_t addr = baseB + (uint32_t)(r * 80 + cc * 2);
                LDMATRIX_X4(bf[nb * 2][0], bf[nb * 2][1],
                            bf[nb * 2 + 1][0], bf[nb * 2 + 1][1], addr);
            }
#pragma unroll
            for (int mt = 0; mt < 4; mt++)
#pragma unroll
                for (int nt = 0; nt < 4; nt++)
                    MMA16816(c[mt][nt][0], c[mt][nt][1],
                             c[mt][nt][2], c[mt][nt][3],
                             a[mt][0], a[mt][1], a[mt][2], a[mt][3],
                             bf[nt][0], bf[nt][1]);
        }
        __syncthreads();
    }

    // epilogue: c fragment (t/4, 2(t%4)+j) and (t/4+8, ...) per tile
    int qr = lane >> 2;            // 0..7
    int qc = (lane & 3) * 2;
#pragma unroll
    for (int mt = 0; mt < 4; mt++) {
        int rbase = m0 + warp_m * 64 + mt * 16 + qr;
#pragma unroll
        for (int nt = 0; nt < 4; nt++) {
            int cbase = n0 + warp_n * 32 + nt * 8 + qc;
            float2 v0 = make_float2(c[mt][nt][0] * alpha, c[mt][nt][1] * alpha);
            float2 v1 = make_float2(c[mt][nt][2] * alpha, c[mt][nt][3] * alpha);
            *(float2*)(C + (size_t)rbase * Ndim + cbase)       = v0;
            *(float2*)(C + (size_t)(rbase + 8) * Ndim + cbase) = v1;
        }
    }
}

// ---------------------------------------------------------------------------
// Attention: one block per (b,h); 128 threads = 128 queries.
// Streaming softmax, fp32 math via packed f32x2 FMA. Writes f16 output.
// ---------------------------------------------------------------------------
#define AT_CHUNK 64

__global__ void __launch_bounds__(128)
attention_kernel(const float* __restrict__ q, const float* __restrict__ kv,
                 __half* __restrict__ out) {
    int b = blockIdx.x >> 4;
    int h = blockIdx.x & 15;
    int i = threadIdx.x;

    __shared__ float kk[AT_CHUNK][64];
    __shared__ float vv[AT_CHUNK][64];

    unsigned long long q2[32];
    {
        const ulonglong2* qp =
            (const ulonglong2*)(q + (size_t)(b * M_ + i) * INNER_ + h * DH_);
#pragma unroll
        for (int p = 0; p < 16; p++) {
            ulonglong2 t = qp[p];
            q2[p * 2] = t.x; q2[p * 2 + 1] = t.y;
        }
    }

    float m = -1e30f, l = 0.f;
    unsigned long long acc2[32];
#pragma unroll
    for (int p = 0; p < 32; p++) acc2[p] = 0ull;

    const float* kbase = kv + (size_t)(b * S_) * (2 * INNER_) + h * DH_;

    for (int s0 = 0; s0 < S_; s0 += AT_CHUNK) {
#pragma unroll
        for (int it = 0; it < 8; it++) {
            int idx = threadIdx.x + it * 128;
            int r   = idx >> 4;
            int c4  = idx & 15;
            const float* src = kbase + (size_t)(s0 + r) * (2 * INNER_) + c4 * 4;
            *(float4*)&kk[r][c4 * 4] = *(const float4*)src;
            *(float4*)&vv[r][c4 * 4] = *(const float4*)(src + INNER_);
        }
        __syncthreads();

        for (int j = 0; j < AT_CHUNK; j++) {
            unsigned long long sa = 0ull, sb = 0ull, sc = 0ull, sd = 0ull;
            const ulonglong2* kj = (const ulonglong2*)kk[j];
#pragma unroll
            for (int p = 0; p < 16; p += 2) {
                ulonglong2 ka = kj[p];
                ulonglong2 kb = kj[p + 1];
                sa = ffma2(q2[p * 2 + 0], ka.x, sa);
                sb = ffma2(q2[p * 2 + 1], ka.y, sb);
                sc = ffma2(q2[p * 2 + 2], kb.x, sc);
                sd = ffma2(q2[p * 2 + 3], kb.y, sd);
            }
            float a0, a1, b0, b1, c0, c1, d0, d1;
            upk2(sa, a0, a1); upk2(sb, b0, b1);
            upk2(sc, c0, c1); upk2(sd, d0, d1);
            float s = ((a0 + a1) + (b0 + b1)) + ((c0 + c1) + (d0 + d1));

            const ulonglong2* vj = (const ulonglong2*)vv[j];
            if (s <= m) {
                float p = __expf(s - m);
                l += p;
                unsigned long long p2 = pk2(p, p);
#pragma unroll
                for (int pp = 0; pp < 16; pp++) {
                    ulonglong2 v4 = vj[pp];
                    acc2[pp * 2]     = ffma2(p2, v4.x, acc2[pp * 2]);
                    acc2[pp * 2 + 1] = ffma2(p2, v4.y, acc2[pp * 2 + 1]);
                }
            } else {
                float f = __expf(m - s);
                m = s;
                l = l * f + 1.f;
                unsigned long long f2 = pk2(f, f);
#pragma unroll
                for (int pp = 0; pp < 16; pp++) {
                    ulonglong2 v4 = vj[pp];
                    acc2[pp * 2]     = ffma2(acc2[pp * 2],     f2, v4.x);
                    acc2[pp * 2 + 1] = ffma2(acc2[pp * 2 + 1], f2, v4.y);
                }
            }
        }
        __syncthreads();
    }

    float inv = 1.f / l;
    __half2* op = (__half2*)(out + (size_t)(b * M_ + i) * INNER_ + h * DH_);
#pragma unroll
    for (int p = 0; p < 32; p++) {
        float lo, hi;
        upk2(acc2[p], lo, hi);
        op[p] = __floats2half2_rn(lo * inv, hi * inv);
    }
}

// ---------------------------------------------------------------------------
// Launch
// ---------------------------------------------------------------------------
extern "C" void kernel_launch(void* const* d_in, const int* in_sizes, int n_in,
                              void* d_out, int out_size) {
    const float* x       = (const float*)d_in[0];
    const float* latents = (const float*)d_in[1];
    const float* gx      = (const float*)d_in[2];
    const float* bx      = (const float*)d_in[3];
    const float* gl      = (const float*)d_in[4];
    const float* bl      = (const float*)d_in[5];
    const float* Wq      = (const float*)d_in[6];
    const float* Wkv     = (const float*)d_in[7];
    const float* Wo      = (const float*)d_in[8];
    float* out = (float*)d_out;

    __half *xnh, *lnh, *Wqh, *Wkvh, *Woh, *ath;
    float *qb, *kvb;
    cudaGetSymbolAddress((void**)&xnh,  g_xnh);
    cudaGetSymbolAddress((void**)&lnh,  g_lnh);
    cudaGetSymbolAddress((void**)&Wqh,  g_Wqh);
    cudaGetSymbolAddress((void**)&Wkvh, g_Wkvh);
    cudaGetSymbolAddress((void**)&Woh,  g_Woh);
    cudaGetSymbolAddress((void**)&qb,   g_q);
    cudaGetSymbolAddress((void**)&kvb,  g_kv);
    cudaGetSymbolAddress((void**)&ath,  g_ath);

    // LayerNorms (f16 out)
    layernorm_h_kernel<<<B_ * S_, 256>>>(x, gx, bx, xnh);
    layernorm_h_kernel<<<B_ * M_, 256>>>(latents, gl, bl, lnh);

    // Weight converts
    conv_f2h<<<(INNER_ * D_ / 4 + 255) / 256, 256>>>(Wq, Wqh, INNER_ * D_ / 4);
    conv_f2h<<<(2 * INNER_ * D_ / 4 + 255) / 256, 256>>>(Wkv, Wkvh,
                                                         2 * INNER_ * D_ / 4);
    conv_f2h<<<(D_ * INNER_ / 4 + 255) / 256, 256>>>(Wo, Woh, D_ * INNER_ / 4);

    // q = 0.125 * ln @ Wq^T   (M=2048, N=1024, K=1024)
    hgemm_mma<<<dim3(INNER_ / BN, (B_ * M_) / BM), 256>>>(
        lnh, Wqh, qb, D_, INNER_, 0.125f);

    // kv = xn @ Wkv^T         (M=32768, N=2048, K=1024) — dominant GEMM
    hgemm_mma<<<dim3((2 * INNER_) / BN, (B_ * S_) / BM), 256>>>(
        xnh, Wkvh, kvb, D_, 2 * INNER_, 1.f);

    // attention per (b,h), f16 out
    attention_kernel<<<B_ * H_, 128>>>(qb, kvb, ath);

    // out = attn @ Wo^T       (M=2048, N=1024, K=1024)
    hgemm_mma<<<dim3(D_ / BN, (B_ * M_) / BM), 256>>>(
        ath, Woh, out, INNER_, D_, 1.f);
}

// round 10
// speedup vs baseline: 2.3135x; 2.3135x over previous
#include <cuda_runtime.h>
#include <cuda_fp16.h>
#include <cstdint>
#include <math.h>

// Problem constants
#define B_    16
#define S_    2048
#define D_    1024
#define M_    128
#define H_    16
#define DH_   64
#define INNER_ 1024

// ---------------------------------------------------------------------------
// Scratch (static device arrays: alloc APIs are forbidden)
// ---------------------------------------------------------------------------
__device__ __half g_xnh [B_ * S_ * D_];           // 67 MB  (LN(x) f16)
__device__ __half g_lnh [B_ * M_ * D_];           // 4 MB
__device__ __half g_Wqh [INNER_ * D_];            // 2 MB
__device__ __half g_Wkvh[2 * INNER_ * D_];        // 4 MB
__device__ __half g_Woh [D_ * INNER_];            // 2 MB
__device__ __half g_qh  [B_ * M_ * INNER_];       // 4 MB  (f16 q, pre-scaled)
__device__ __half g_kvh [B_ * S_ * 2 * INNER_];   // 134 MB (f16 kv)
__device__ __half g_ath [B_ * M_ * INNER_];       // 4 MB  (attention out f16)

// ---------------------------------------------------------------------------
// Helpers
// ---------------------------------------------------------------------------
__device__ __forceinline__ uint32_t smem_u32(const void* p) {
    uint32_t a;
    asm("{ .reg .u64 t; cvta.to.shared.u64 t, %1; cvt.u32.u64 %0, t; }"
        : "=r"(a) : "l"(p));
    return a;
}

#define CP_ASYNC16(dst, src) \
    asm volatile("cp.async.cg.shared.global [%0], [%1], 16;" \
                 :: "r"(dst), "l"(src))
#define CP_COMMIT() asm volatile("cp.async.commit_group;" ::: "memory")
#define CP_WAIT(n)  asm volatile("cp.async.wait_group %0;" :: "n"(n) : "memory")

#define LDMATRIX_X4(r0, r1, r2, r3, addr) \
    asm volatile("ldmatrix.sync.aligned.m8n8.x4.shared.b16 {%0,%1,%2,%3}, [%4];" \
                 : "=r"(r0), "=r"(r1), "=r"(r2), "=r"(r3) : "r"(addr))

#define LDMATRIX_X4_T(r0, r1, r2, r3, addr) \
    asm volatile("ldmatrix.sync.aligned.m8n8.x4.trans.shared.b16 {%0,%1,%2,%3}, [%4];" \
                 : "=r"(r0), "=r"(r1), "=r"(r2), "=r"(r3) : "r"(addr))

#define MMA16816(c0, c1, c2, c3, a0, a1, a2, a3, b0, b1) \
    asm volatile("mma.sync.aligned.m16n8k16.row.col.f32.f16.f16.f32 " \
                 "{%0,%1,%2,%3}, {%4,%5,%6,%7}, {%8,%9}, {%0,%1,%2,%3};" \
                 : "+f"(c0), "+f"(c1), "+f"(c2), "+f"(c3) \
                 : "r"(a0), "r"(a1), "r"(a2), "r"(a3), "r"(b0), "r"(b1))

__device__ __forceinline__ uint32_t h2_u32(float lo, float hi) {
    __half2 h = __floats2half2_rn(lo, hi);
    return *reinterpret_cast<uint32_t*>(&h);
}

// ---------------------------------------------------------------------------
// LayerNorm: one block per row of 1024, 256 threads, f16 output
// ---------------------------------------------------------------------------
__global__ void __launch_bounds__(256)
layernorm_h_kernel(const float* __restrict__ x, const float* __restrict__ gamma,
                   const float* __restrict__ beta, __half* __restrict__ out) {
    int row = blockIdx.x;
    int t   = threadIdx.x;
    const float4* xr = (const float4*)(x + (size_t)row * D_);
    float4 v = xr[t];
    float s  = v.x + v.y + v.z + v.w;
    float ss = v.x * v.x + v.y * v.y + v.z * v.z + v.w * v.w;

    __shared__ float red[64];
    const unsigned mask = 0xffffffffu;
#pragma unroll
    for (int o = 16; o > 0; o >>= 1) {
        s  += __shfl_xor_sync(mask, s, o);
        ss += __shfl_xor_sync(mask, ss, o);
    }
    int wid = t >> 5, lane = t & 31;
    if (lane == 0) { red[wid] = s; red[32 + wid] = ss; }
    __syncthreads();
    if (t < 32) {
        float s2  = (lane < 8) ? red[lane]      : 0.f;
        float ss2 = (lane < 8) ? red[32 + lane] : 0.f;
#pragma unroll
        for (int o = 4; o > 0; o >>= 1) {
            s2  += __shfl_xor_sync(mask, s2, o);
            ss2 += __shfl_xor_sync(mask, ss2, o);
        }
        if (lane == 0) { red[0] = s2; red[1] = ss2; }
    }
    __syncthreads();
    float mu   = red[0] * (1.f / D_);
    float var  = red[1] * (1.f / D_) - mu * mu;
    float rstd = rsqrtf(var + 1e-5f);

    float4 g  = ((const float4*)gamma)[t];
    float4 bb = ((const float4*)beta)[t];
    float ox = (v.x - mu) * rstd * g.x + bb.x;
    float oy = (v.y - mu) * rstd * g.y + bb.y;
    float oz = (v.z - mu) * rstd * g.z + bb.z;
    float ow = (v.w - mu) * rstd * g.w + bb.w;
    __half2* op = (__half2*)(out + (size_t)row * D_);
    op[t * 2]     = __floats2half2_rn(ox, oy);
    op[t * 2 + 1] = __floats2half2_rn(oz, ow);
}

// ---------------------------------------------------------------------------
// fp32 -> fp16 convert (weights)
// ---------------------------------------------------------------------------
__global__ void __launch_bounds__(256)
conv_f2h(const float* __restrict__ in, __half* __restrict__ out, int n4) {
    int i = blockIdx.x * 256 + threadIdx.x;
    if (i < n4) {
        float4 v = ((const float4*)in)[i];
        __half2* op = (__half2*)out;
        op[i * 2]     = __floats2half2_rn(v.x, v.y);
        op[i * 2 + 1] = __floats2half2_rn(v.z, v.w);
    }
}

// ---------------------------------------------------------------------------
// HGEMM via mma.sync (HMMA): C[M,N] = alpha * A_h[M,K] @ B_h[N,K]^T
// Fragment maps validated in round 6. Now 3-stage cp.async pipeline
// (2 k-tiles in flight) in dynamic smem: 3 x (A+B) buffers = 61440 B.
// ---------------------------------------------------------------------------
#define BM 128
#define BN 128
#define BKH 32
#define TILE_H (BM * 40)         // padded rows: 40 halfs (80B) stride
#define NSTAGE 3
#define HG_DSMEM (NSTAGE * 2 * TILE_H * 2)   // bytes

template <typename OT>
__global__ void __launch_bounds__(256)
hgemm_mma(const __half* __restrict__ A, const __half* __restrict__ B,
          OT* __restrict__ C, int Kdim, int Ndim, float alpha) {
    extern __shared__ __half dsm[];
    // layout: [stage][A tile][B tile] grouped as A[3] then B[3]
    uint32_t sAu = smem_u32(dsm);
    uint32_t sBu = sAu + NSTAGE * TILE_H * 2;

    int tid    = threadIdx.x;
    int lane   = tid & 31;
    int wid    = tid >> 5;
    int warp_m = wid & 1;
    int warp_n = wid >> 1;
    int m0     = blockIdx.y * BM;
    int n0     = blockIdx.x * BN;

    const __half* Ab = A + (size_t)m0 * Kdim;
    const __half* Bb = B + (size_t)n0 * Kdim;

    float c[4][4][4];
#pragma unroll
    for (int i = 0; i < 4; i++)
#pragma unroll
        for (int j = 0; j < 4; j++)
#pragma unroll
            for (int k = 0; k < 4; k++) c[i][j][k] = 0.f;

    int r0 = tid >> 2;
    int c0chunk = tid & 3;
    int r1 = (tid + 256) >> 2;
    uint32_t offA0 = (uint32_t)(r0 * 80 + c0chunk * 16);
    uint32_t offA1 = (uint32_t)(r1 * 80 + c0chunk * 16);

    int NT = Kdim / BKH;

    // prologue: issue tiles 0 and 1 (one commit group each)
#pragma unroll
    for (int s = 0; s < 2; s++) {
        int k0 = s * BKH;
        uint32_t boff = (uint32_t)(s * TILE_H * 2);
        CP_ASYNC16(sAu + boff + offA0, Ab + (size_t)r0 * Kdim + k0 + c0chunk * 8);
        CP_ASYNC16(sAu + boff + offA1, Ab + (size_t)r1 * Kdim + k0 + c0chunk * 8);
        CP_ASYNC16(sBu + boff + offA0, Bb + (size_t)r0 * Kdim + k0 + c0chunk * 8);
        CP_ASYNC16(sBu + boff + offA1, Bb + (size_t)r1 * Kdim + k0 + c0chunk * 8);
        CP_COMMIT();
    }

    for (int kt = 0; kt < NT; kt++) {
        int buf = kt % NSTAGE;

        if (kt + 2 < NT) {
            int nb = (kt + 2) % NSTAGE;
            int k0 = (kt + 2) * BKH;
            uint32_t boff = (uint32_t)(nb * TILE_H * 2);
            CP_ASYNC16(sAu + boff + offA0,
                       Ab + (size_t)r0 * Kdim + k0 + c0chunk * 8);
            CP_ASYNC16(sAu + boff + offA1,
                       Ab + (size_t)r1 * Kdim + k0 + c0chunk * 8);
            CP_ASYNC16(sBu + boff + offA0,
                       Bb + (size_t)r0 * Kdim + k0 + c0chunk * 8);
            CP_ASYNC16(sBu + boff + offA1,
                       Bb + (size_t)r1 * Kdim + k0 + c0chunk * 8);
            CP_COMMIT();
            CP_WAIT(2);               // tile kt complete; kt+1, kt+2 in flight
        } else if (kt + 1 < NT) {
            CP_WAIT(1);               // tile kt complete; kt+1 in flight
        } else {
            CP_WAIT(0);               // last tile complete
        }
        __syncthreads();

        uint32_t baseA = sAu + (uint32_t)(buf * TILE_H * 2);
        uint32_t baseB = sBu + (uint32_t)(buf * TILE_H * 2);

#pragma unroll
        for (int kk = 0; kk < BKH; kk += 16) {
            uint32_t a[4][4];
#pragma unroll
            for (int mt = 0; mt < 4; mt++) {
                int r = warp_m * 64 + mt * 16 + (lane & 15);
                int cc = kk + ((lane >> 4) << 3);
                LDMATRIX_X4(a[mt][0], a[mt][1], a[mt][2], a[mt][3],
                            baseA + (uint32_t)(r * 80 + cc * 2));
            }
            uint32_t bf[4][2];
#pragma unroll
            for (int nb = 0; nb < 2; nb++) {
                int r = warp_n * 32 + nb * 16 + (lane & 7) + ((lane >> 4) << 3);
                int cc = kk + (((lane >> 3) & 1) << 3);
                LDMATRIX_X4(bf[nb * 2][0], bf[nb * 2][1],
                            bf[nb * 2 + 1][0], bf[nb * 2 + 1][1],
                            baseB + (uint32_t)(r * 80 + cc * 2));
            }
#pragma unroll
            for (int mt = 0; mt < 4; mt++)
#pragma unroll
                for (int nt = 0; nt < 4; nt++)
                    MMA16816(c[mt][nt][0], c[mt][nt][1],
                             c[mt][nt][2], c[mt][nt][3],
                             a[mt][0], a[mt][1], a[mt][2], a[mt][3],
                             bf[nt][0], bf[nt][1]);
        }
        __syncthreads();   // all reads of buf done before tile kt+3 overwrites
    }

    int qr = lane >> 2;
    int qc = (lane & 3) * 2;
#pragma unroll
    for (int mt = 0; mt < 4; mt++) {
        int rbase = m0 + warp_m * 64 + mt * 16 + qr;
#pragma unroll
        for (int nt = 0; nt < 4; nt++) {
            int cbase = n0 + warp_n * 32 + nt * 8 + qc;
            if constexpr (sizeof(OT) == 2) {
                __half2 v0 = __floats2half2_rn(c[mt][nt][0] * alpha,
                                               c[mt][nt][1] * alpha);
                __half2 v1 = __floats2half2_rn(c[mt][nt][2] * alpha,
                                               c[mt][nt][3] * alpha);
                *(__half2*)((__half*)C + (size_t)rbase * Ndim + cbase)       = v0;
                *(__half2*)((__half*)C + (size_t)(rbase + 8) * Ndim + cbase) = v1;
            } else {
                float2 v0 = make_float2(c[mt][nt][0] * alpha, c[mt][nt][1] * alpha);
                float2 v1 = make_float2(c[mt][nt][2] * alpha, c[mt][nt][3] * alpha);
                *(float2*)((float*)C + (size_t)rbase * Ndim + cbase)       = v0;
                *(float2*)((float*)C + (size_t)(rbase + 8) * Ndim + cbase) = v1;
            }
        }
    }
}

// ---------------------------------------------------------------------------
// Flash attention with HMMA. One CTA per (b,h); 8 warps x 16 q-rows = 128.
// 64-key chunks; K-major k in smem (scores = validated NT fragment maps);
// row-major v + ldmatrix.trans for P@V; FA2 C->A fragment re-pack for P.
// q pre-scaled by 0.125 in the q GEMM. (Audited R7/R8; unchanged.)
// ---------------------------------------------------------------------------
#define FA_CH 64
#define FSTR  72                 // padded row stride in halfs (144B)

__global__ void __launch_bounds__(256)
fa_kernel(const __half* __restrict__ qh, const __half* __restrict__ kvh,
          __half* __restrict__ out) {
    __shared__ __half sQ[128 * FSTR];     // 18432 B
    __shared__ __half sK[FA_CH * FSTR];   // 9216 B
    __shared__ __half sV[FA_CH * FSTR];   // 9216 B

    int b    = blockIdx.x >> 4;
    int h    = blockIdx.x & 15;
    int tid  = threadIdx.x;
    int lane = tid & 31;
    int w    = tid >> 5;

    uint32_t sQu = smem_u32(sQ), sKu = smem_u32(sK), sVu = smem_u32(sV);

    // async-load the whole Q tile (128 x 64 halfs)
    const __half* qbase = qh + (size_t)(b * M_) * INNER_ + h * DH_;
#pragma unroll
    for (int it = 0; it < 4; it++) {
        int idx = tid + it * 256;         // 0..1023
        int row = idx >> 3, c8 = idx & 7;
        CP_ASYNC16(sQu + (uint32_t)(row * FSTR + c8 * 8) * 2,
                   qbase + (size_t)row * INNER_ + c8 * 8);
    }
    CP_COMMIT();

    const __half* kbase = kvh + (size_t)(b * S_) * (2 * INNER_) + h * DH_;

    float m0 = -1e30f, m1 = -1e30f, l0 = 0.f, l1 = 0.f;
    float oa[8][4];
#pragma unroll
    for (int nt = 0; nt < 8; nt++)
#pragma unroll
        for (int j = 0; j < 4; j++) oa[nt][j] = 0.f;

    for (int cch = 0; cch < S_ / FA_CH; cch++) {
        int s0 = cch * FA_CH;
        // load K,V chunk (64 keys x 64 dims each)
#pragma unroll
        for (int it = 0; it < 2; it++) {
            int idx = tid + it * 256;     // 0..511
            int row = idx >> 3, c8 = idx & 7;
            const __half* src = kbase + (size_t)(s0 + row) * (2 * INNER_) + c8 * 8;
            CP_ASYNC16(sKu + (uint32_t)(row * FSTR + c8 * 8) * 2, src);
            CP_ASYNC16(sVu + (uint32_t)(row * FSTR + c8 * 8) * 2, src + INNER_);
        }
        CP_COMMIT();
        CP_WAIT(0);
        __syncthreads();

        // ----- scores: 16 (rows) x 64 (keys) per warp -----
        float sc[8][4];
#pragma unroll
        for (int nt = 0; nt < 8; nt++)
#pragma unroll
            for (int j = 0; j < 4; j++) sc[nt][j] = 0.f;

#pragma unroll
        for (int kk = 0; kk < 64; kk += 16) {
            uint32_t a0, a1, a2, a3;
            {
                int r  = w * 16 + (lane & 15);
                int cc = kk + ((lane >> 4) << 3);
                LDMATRIX_X4(a0, a1, a2, a3, sQu + (uint32_t)(r * FSTR + cc) * 2);
            }
            uint32_t bk[8][2];
#pragma unroll
            for (int np = 0; np < 4; np++) {
                int r  = np * 16 + (lane & 7) + ((lane >> 4) << 3);
                int cc = kk + (((lane >> 3) & 1) << 3);
                LDMATRIX_X4(bk[np * 2][0], bk[np * 2][1],
                            bk[np * 2 + 1][0], bk[np * 2 + 1][1],
                            sKu + (uint32_t)(r * FSTR + cc) * 2);
            }
#pragma unroll
            for (int nt = 0; nt < 8; nt++)
                MMA16816(sc[nt][0], sc[nt][1], sc[nt][2], sc[nt][3],
                         a0, a1, a2, a3, bk[nt][0], bk[nt][1]);
        }

        // ----- streaming softmax update -----
        const unsigned fmask = 0xffffffffu;
        float mx0 = sc[0][0], mx1 = sc[0][2];
#pragma unroll
        for (int nt = 0; nt < 8; nt++) {
            mx0 = fmaxf(mx0, fmaxf(sc[nt][0], sc[nt][1]));
            mx1 = fmaxf(mx1, fmaxf(sc[nt][2], sc[nt][3]));
        }
        mx0 = fmaxf(mx0, __shfl_xor_sync(fmask, mx0, 1));
        mx0 = fmaxf(mx0, __shfl_xor_sync(fmask, mx0, 2));
        mx1 = fmaxf(mx1, __shfl_xor_sync(fmask, mx1, 1));
        mx1 = fmaxf(mx1, __shfl_xor_sync(fmask, mx1, 2));

        float mn0 = fmaxf(m0, mx0), mn1 = fmaxf(m1, mx1);
        float rf0 = __expf(m0 - mn0), rf1 = __expf(m1 - mn1);

        uint32_t plo[8], phi[8];
        float rs0 = 0.f, rs1 = 0.f;
#pragma unroll
        for (int nt = 0; nt < 8; nt++) {
            float p0 = __expf(sc[nt][0] - mn0);
            float p1 = __expf(sc[nt][1] - mn0);
            float p2 = __expf(sc[nt][2] - mn1);
            float p3 = __expf(sc[nt][3] - mn1);
            rs0 += p0 + p1;
            rs1 += p2 + p3;
            plo[nt] = h2_u32(p0, p1);    // row r, k pair
            phi[nt] = h2_u32(p2, p3);    // row r+8, k pair
        }
        rs0 += __shfl_xor_sync(fmask, rs0, 1);
        rs0 += __shfl_xor_sync(fmask, rs0, 2);
        rs1 += __shfl_xor_sync(fmask, rs1, 1);
        rs1 += __shfl_xor_sync(fmask, rs1, 2);

        l0 = l0 * rf0 + rs0;
        l1 = l1 * rf1 + rs1;
        m0 = mn0; m1 = mn1;
#pragma unroll
        for (int nt = 0; nt < 8; nt++) {
            oa[nt][0] *= rf0; oa[nt][1] *= rf0;
            oa[nt][2] *= rf1; oa[nt][3] *= rf1;
        }

        // ----- out += P @ V -----
#pragma unroll
        for (int ks = 0; ks < 4; ks++) {
            uint32_t a0 = plo[2 * ks],     a1 = phi[2 * ks];
            uint32_t a2 = plo[2 * ks + 1], a3 = phi[2 * ks + 1];
            uint32_t bv[8][2];
#pragma unroll
            for (int dt = 0; dt < 4; dt++) {
                int r  = ks * 16 + (((lane >> 3) & 1) << 3) + (lane & 7);
                int cc = dt * 16 + ((lane >> 4) << 3);
                LDMATRIX_X4_T(bv[dt * 2][0], bv[dt * 2][1],
                              bv[dt * 2 + 1][0], bv[dt * 2 + 1][1],
                              sVu + (uint32_t)(r * FSTR + cc) * 2);
            }
#pragma unroll
            for (int nt = 0; nt < 8; nt++)
                MMA16816(oa[nt][0], oa[nt][1], oa[nt][2], oa[nt][3],
                         a0, a1, a2, a3, bv[nt][0], bv[nt][1]);
        }
        __syncthreads();
    }

    // ----- epilogue -----
    float inv0 = 1.f / l0, inv1 = 1.f / l1;
    int r0   = lane >> 2;
    int row0 = w * 16 + r0;
    int colb = h * DH_ + (lane & 3) * 2;
#pragma unroll
    for (int nt = 0; nt < 8; nt++) {
        int col = colb + nt * 8;
        __half2 v0 = __floats2half2_rn(oa[nt][0] * inv0, oa[nt][1] * inv0);
        __half2 v1 = __floats2half2_rn(oa[nt][2] * inv1, oa[nt][3] * inv1);
        *(__half2*)(out + (size_t)(b * M_ + row0) * INNER_ + col)     = v0;
        *(__half2*)(out + (size_t)(b * M_ + row0 + 8) * INNER_ + col) = v1;
    }
}

// ---------------------------------------------------------------------------
// Launch
// ---------------------------------------------------------------------------
extern "C" void kernel_launch(void* const* d_in, const int* in_sizes, int n_in,
                              void* d_out, int out_size) {
    const float* x       = (const float*)d_in[0];
    const float* latents = (const float*)d_in[1];
    const float* gx      = (const float*)d_in[2];
    const float* bx      = (const float*)d_in[3];
    const float* gl      = (const float*)d_in[4];
    const float* bl      = (const float*)d_in[5];
    const float* Wq      = (const float*)d_in[6];
    const float* Wkv     = (const float*)d_in[7];
    const float* Wo      = (const float*)d_in[8];
    float* out = (float*)d_out;

    __half *xnh, *lnh, *Wqh, *Wkvh, *Woh, *qh, *kvh, *ath;
    cudaGetSymbolAddress((void**)&xnh,  g_xnh);
    cudaGetSymbolAddress((void**)&lnh,  g_lnh);
    cudaGetSymbolAddress((void**)&Wqh,  g_Wqh);
    cudaGetSymbolAddress((void**)&Wkvh, g_Wkvh);
    cudaGetSymbolAddress((void**)&Woh,  g_Woh);
    cudaGetSymbolAddress((void**)&qh,   g_qh);
    cudaGetSymbolAddress((void**)&kvh,  g_kvh);
    cudaGetSymbolAddress((void**)&ath,  g_ath);

    // opt-in to 60KB dynamic smem for both GEMM instantiations
    cudaFuncSetAttribute(hgemm_mma<__half>,
                         cudaFuncAttributeMaxDynamicSharedMemorySize, HG_DSMEM);
    cudaFuncSetAttribute(hgemm_mma<float>,
                         cudaFuncAttributeMaxDynamicSharedMemorySize, HG_DSMEM);

    // LayerNorms (f16 out)
    layernorm_h_kernel<<<B_ * S_, 256>>>(x, gx, bx, xnh);
    layernorm_h_kernel<<<B_ * M_, 256>>>(latents, gl, bl, lnh);

    // Weight converts
    conv_f2h<<<(INNER_ * D_ / 4 + 255) / 256, 256>>>(Wq, Wqh, INNER_ * D_ / 4);
    conv_f2h<<<(2 * INNER_ * D_ / 4 + 255) / 256, 256>>>(Wkv, Wkvh,
                                                         2 * INNER_ * D_ / 4);
    conv_f2h<<<(D_ * INNER_ / 4 + 255) / 256, 256>>>(Wo, Woh, D_ * INNER_ / 4);

    // q = 0.125 * ln @ Wq^T  (f16 out)
    hgemm_mma<__half><<<dim3(INNER_ / BN, (B_ * M_) / BM), 256, HG_DSMEM>>>(
        lnh, Wqh, qh, D_, INNER_, 0.125f);

    // kv = xn @ Wkv^T  (f16 out; dominant GEMM)
    hgemm_mma<__half><<<dim3((2 * INNER_) / BN, (B_ * S_) / BM), 256, HG_DSMEM>>>(
        xnh, Wkvh, kvh, D_, 2 * INNER_, 1.f);

    // flash attention per (b,h)
    fa_kernel<<<B_ * H_, 256>>>(qh, kvh, ath);

    // out = attn @ Wo^T  (fp32 out)
    hgemm_mma<float><<<dim3(D_ / BN, (B_ * M_) / BM), 256, HG_DSMEM>>>(
        ath, Woh, out, INNER_, D_, 1.f);
}